// round 1
// baseline (speedup 1.0000x reference)
#include <cuda_runtime.h>
#include <cstddef>

#define TT 1024
#define BB 4096
#define II 5
#define NH0 15
#define NH1 10
#define NH2 2

__device__ __forceinline__ float tanh_fast(float v) {
    float r;
    asm("tanh.approx.f32 %0, %1;" : "=f"(r) : "f"(v));
    return r;
}
__device__ __forceinline__ float sig_fast(float v) {
    return fmaf(0.5f, tanh_fast(0.5f * v), 0.5f);
}

// Dot product over P (multiple of 4) padded floats: w from SMEM (16B aligned,
// zero padded), v in registers. Two accumulators for ILP.
template <int P>
__device__ __forceinline__ float dotP(const float* __restrict__ w, const float* v) {
    float s0 = 0.f, s1 = 0.f;
#pragma unroll
    for (int i = 0; i < P / 4; ++i) {
        float4 ww = *reinterpret_cast<const float4*>(w + 4 * i);
        s0 = fmaf(ww.x, v[4 * i + 0], s0);
        s1 = fmaf(ww.y, v[4 * i + 1], s1);
        s0 = fmaf(ww.z, v[4 * i + 2], s0);
        s1 = fmaf(ww.w, v[4 * i + 3], s1);
    }
    return s0 + s1;
}

// CTA: 32 batch elements x 8 role-warps (warp w = role w for 32 elements).
// Roles 0-3: layer0 units {0-3,4-7,8-11,12-14}
// Roles 4-7: layer1 units {0-2,3-5,6-7,8-9}; roles 6,7 also own layer2 unit 0,1.
// Skewed pipeline: iter k computes h0[k], h1[k-1], h2[k-2]; one barrier/iter.
__global__ __launch_bounds__(256, 1) void gru_fused(
    const float* __restrict__ x,
    const float* __restrict__ wih0, const float* __restrict__ whh0,
    const float* __restrict__ bih0, const float* __restrict__ bhh0,
    const float* __restrict__ wih1, const float* __restrict__ whh1,
    const float* __restrict__ bih1, const float* __restrict__ bhh1,
    const float* __restrict__ wih2, const float* __restrict__ whh2,
    const float* __restrict__ bih2, const float* __restrict__ bhh2,
    float* __restrict__ out)
{
    // Weights padded to float4-multiple rows (zeros in pad).
    __shared__ float s_wih0[45 * 8];   // rows of 5 -> 8
    __shared__ float s_whh0[45 * 16];  // 15 -> 16
    __shared__ float s_wih1[30 * 16];  // 15 -> 16
    __shared__ float s_whh1[30 * 12];  // 10 -> 12
    __shared__ float s_wih2[6 * 12];   // 10 -> 12
    __shared__ float s_whh2[6 * 4];    // 2 -> 4
    __shared__ float s_bih0[45], s_bhh0[45];
    __shared__ float s_bih1[30], s_bhh1[30];
    __shared__ float s_bih2[6], s_bhh2[6];
    // Double-buffered state: [buf][unit][elem] -> lane reads conflict-free.
    __shared__ float s_h0[2][NH0][32];
    __shared__ float s_h1[2][NH1][32];
    __shared__ float s_h2[2][NH2][32];
    __shared__ float s_x[2][32 * II];

    const int tid = threadIdx.x;
    const int lane = tid & 31;
    const int role = tid >> 5;

    for (int i = tid; i < 45 * 8; i += 256) {
        int u = i >> 3, c = i & 7;
        s_wih0[i] = (c < 5) ? wih0[u * 5 + c] : 0.f;
    }
    for (int i = tid; i < 45 * 16; i += 256) {
        int u = i >> 4, c = i & 15;
        s_whh0[i] = (c < 15) ? whh0[u * 15 + c] : 0.f;
    }
    for (int i = tid; i < 30 * 16; i += 256) {
        int u = i >> 4, c = i & 15;
        s_wih1[i] = (c < 15) ? wih1[u * 15 + c] : 0.f;
    }
    for (int i = tid; i < 30 * 12; i += 256) {
        int u = i / 12, c = i % 12;
        s_whh1[i] = (c < 10) ? whh1[u * 10 + c] : 0.f;
    }
    for (int i = tid; i < 6 * 12; i += 256) {
        int u = i / 12, c = i % 12;
        s_wih2[i] = (c < 10) ? wih2[u * 10 + c] : 0.f;
    }
    for (int i = tid; i < 6 * 4; i += 256) {
        int u = i >> 2, c = i & 3;
        s_whh2[i] = (c < 2) ? whh2[u * 2 + c] : 0.f;
    }
    for (int i = tid; i < 45; i += 256) { s_bih0[i] = bih0[i]; s_bhh0[i] = bhh0[i]; }
    for (int i = tid; i < 30; i += 256) { s_bih1[i] = bih1[i]; s_bhh1[i] = bhh1[i]; }
    if (tid < 6) { s_bih2[tid] = bih2[tid]; s_bhh2[tid] = bhh2[tid]; }
    for (int i = tid; i < 2 * NH0 * 32; i += 256) (&s_h0[0][0][0])[i] = 0.f;
    for (int i = tid; i < 2 * NH1 * 32; i += 256) (&s_h1[0][0][0])[i] = 0.f;
    for (int i = tid; i < 2 * NH2 * 32; i += 256) (&s_h2[0][0][0])[i] = 0.f;
    if (tid < 32 * II)
        s_x[0][tid] = x[(size_t)blockIdx.x * (32 * II) + tid];
    __syncthreads();

    const int ge = blockIdx.x * 32 + lane;

    for (int k = 0; k < TT + 2; ++k) {
        const int bi = k & 1;
        const int bo = bi ^ 1;

        // Prefetch x[k+1] (hidden under compute).
        float xpre = 0.f;
        const bool pf = (k + 1 < TT) && (tid < 32 * II);
        if (pf)
            xpre = x[(size_t)(k + 1) * (BB * II) + (size_t)blockIdx.x * (32 * II) + tid];

        if (role < 4) {
            // -------- Layer 0: compute h0[k] --------
            if (k < TT) {
                float xv[8], hv[16];
#pragma unroll
                for (int c = 0; c < 5; ++c) xv[c] = s_x[bi][lane * 5 + c];
                xv[5] = xv[6] = xv[7] = 0.f;
#pragma unroll
                for (int j = 0; j < 15; ++j) hv[j] = s_h0[bi][j][lane];
                hv[15] = 0.f;
                const int u0 = role * 4;
                const int u1 = (role == 3) ? 15 : u0 + 4;
                for (int u = u0; u < u1; ++u) {
                    float xr = dotP<8>(s_wih0 + u * 8, xv) + s_bih0[u];
                    float xz = dotP<8>(s_wih0 + (15 + u) * 8, xv) + s_bih0[15 + u];
                    float xn = dotP<8>(s_wih0 + (30 + u) * 8, xv) + s_bih0[30 + u];
                    float hr = dotP<16>(s_whh0 + u * 16, hv) + s_bhh0[u];
                    float hz = dotP<16>(s_whh0 + (15 + u) * 16, hv) + s_bhh0[15 + u];
                    float hn = dotP<16>(s_whh0 + (30 + u) * 16, hv) + s_bhh0[30 + u];
                    float r = sig_fast(xr + hr);
                    float z = sig_fast(xz + hz);
                    float n = tanh_fast(fmaf(r, hn, xn));
                    s_h0[bo][u][lane] = fmaf(z, hv[u] - n, n);
                }
            }
        } else {
            // -------- Layer 1: compute h1[k-1] from o0[k-1]=s_h0[bi] --------
            if (k >= 1 && k <= TT) {
                float xv[16], hv[12];
#pragma unroll
                for (int j = 0; j < 15; ++j) xv[j] = s_h0[bi][j][lane];
                xv[15] = 0.f;
#pragma unroll
                for (int j = 0; j < 10; ++j) hv[j] = s_h1[bi][j][lane];
                hv[10] = hv[11] = 0.f;
                const int rr = role - 4;
                const int u0 = (rr < 2) ? rr * 3 : 6 + (rr - 2) * 2;
                const int u1 = u0 + ((rr < 2) ? 3 : 2);
                for (int u = u0; u < u1; ++u) {
                    float xr = dotP<16>(s_wih1 + u * 16, xv) + s_bih1[u];
                    float xz = dotP<16>(s_wih1 + (10 + u) * 16, xv) + s_bih1[10 + u];
                    float xn = dotP<16>(s_wih1 + (20 + u) * 16, xv) + s_bih1[20 + u];
                    float hr = dotP<12>(s_whh1 + u * 12, hv) + s_bhh1[u];
                    float hz = dotP<12>(s_whh1 + (10 + u) * 12, hv) + s_bhh1[10 + u];
                    float hn = dotP<12>(s_whh1 + (20 + u) * 12, hv) + s_bhh1[20 + u];
                    float r = sig_fast(xr + hr);
                    float z = sig_fast(xz + hz);
                    float n = tanh_fast(fmaf(r, hn, xn));
                    s_h1[bo][u][lane] = fmaf(z, hv[u] - n, n);
                }
            }
            // -------- Layer 2: compute h2[k-2] from o1[k-2]=s_h1[bi] --------
            if (role >= 6 && k >= 2) {
                float xv2[12], hv2[4];
#pragma unroll
                for (int j = 0; j < 10; ++j) xv2[j] = s_h1[bi][j][lane];
                xv2[10] = xv2[11] = 0.f;
                hv2[0] = s_h2[bi][0][lane];
                hv2[1] = s_h2[bi][1][lane];
                hv2[2] = hv2[3] = 0.f;
                const int u = role - 6;
                float xr = dotP<12>(s_wih2 + u * 12, xv2) + s_bih2[u];
                float xz = dotP<12>(s_wih2 + (2 + u) * 12, xv2) + s_bih2[2 + u];
                float xn = dotP<12>(s_wih2 + (4 + u) * 12, xv2) + s_bih2[4 + u];
                float hr = dotP<4>(s_whh2 + u * 4, hv2) + s_bhh2[u];
                float hz = dotP<4>(s_whh2 + (2 + u) * 4, hv2) + s_bhh2[2 + u];
                float hn = dotP<4>(s_whh2 + (4 + u) * 4, hv2) + s_bhh2[4 + u];
                float r = sig_fast(xr + hr);
                float z = sig_fast(xz + hz);
                float n = tanh_fast(fmaf(r, hn, xn));
                float h2n = fmaf(z, hv2[u] - n, n);
                s_h2[bo][u][lane] = h2n;
                out[(size_t)(k - 2) * (BB * NH2) + ge * 2 + u] = h2n;
            }
        }

        if (pf) s_x[bo][tid] = xpre;
        __syncthreads();
    }
}

extern "C" void kernel_launch(void* const* d_in, const int* in_sizes, int n_in,
                              void* d_out, int out_size) {
    (void)in_sizes; (void)n_in; (void)out_size;
    const float* x    = (const float*)d_in[0];
    const float* wih0 = (const float*)d_in[1];
    const float* whh0 = (const float*)d_in[2];
    const float* bih0 = (const float*)d_in[3];
    const float* bhh0 = (const float*)d_in[4];
    const float* wih1 = (const float*)d_in[5];
    const float* whh1 = (const float*)d_in[6];
    const float* bih1 = (const float*)d_in[7];
    const float* bhh1 = (const float*)d_in[8];
    const float* wih2 = (const float*)d_in[9];
    const float* whh2 = (const float*)d_in[10];
    const float* bih2 = (const float*)d_in[11];
    const float* bhh2 = (const float*)d_in[12];

    gru_fused<<<BB / 32, 256>>>(x, wih0, whh0, bih0, bhh0,
                                wih1, whh1, bih1, bhh1,
                                wih2, whh2, bih2, bhh2,
                                (float*)d_out);
}